// round 2
// baseline (speedup 1.0000x reference)
#include <cuda_runtime.h>
#include <cstdint>
#include <math.h>

// Problem constants
#define HH 256
#define MM 32
#define NIMG 512            // B*C = 64*8
#define NMODES (NIMG*MM*MM) // 524288

typedef unsigned long long u64;

// ---------- scratch (static device globals: no allocation allowed) ----------
__device__ float2 g_modes[2][NIMG][MM * MM]; // [sel][img][k2*32+k1], sel 0=pred 1=gt
__device__ float  g_tot[NIMG];               // per-image total modal energy (pred)

// ---------- f32x2 packed helpers ----------
__device__ __forceinline__ u64 pack2(float lo, float hi) {
    u64 r; asm("mov.b64 %0,{%1,%2};" : "=l"(r) : "f"(lo), "f"(hi)); return r;
}
__device__ __forceinline__ void unpack2(u64 v, float& lo, float& hi) {
    asm("mov.b64 {%0,%1},%2;" : "=f"(lo), "=f"(hi) : "l"(v));
}
__device__ __forceinline__ u64 ffma2(u64 a, u64 b, u64 c) {
    u64 d; asm("fma.rn.f32x2 %0,%1,%2,%3;" : "=l"(d) : "l"(a), "l"(b), "l"(c)); return d;
}

// ============================================================================
// K1: fused partial 2D DFT per image.
//   stage 1: X[k1][n2] = sum_n1 x[n1][n2] * e^{-2pi i k1 n1/256}   (k1 < 32)
//   stage 2: modes[k1][k2] = sum_n2 X[k1][n2] * e^{-2pi i k2 n2/256} (k2 < 32)
// Output layout: g_modes[sel][img][k2*32+k1] (coalesced stores).
// Also fuses per-image total energy (pred only).
// smem layout (68 KB dynamic):
//   [0 .. 2KB)   s_tw[256]  u64  (cos, -sin)
//   [2 .. 4KB)   s_twB[256] u64  (sin,  cos)
//   [4 .. 68KB)  UNION: stage1 s_x[32*256]f (32KB) | stage2 s_X[8192]u64 (64KB)
// ============================================================================
extern __shared__ float smem_raw[];

__global__ void __launch_bounds__(256, 2)
k_dft(const float* __restrict__ pred, const float* __restrict__ gt)
{
    const int img = blockIdx.x;
    const int sel = blockIdx.y;
    const float* __restrict__ x = (sel ? gt : pred) + (size_t)img * (HH * HH);

    u64*   s_tw  = (u64*)smem_raw;             // 256
    u64*   s_twB = s_tw + 256;                 // 256
    float* s_x   = (float*)(s_twB + 256);      // 8192 floats (stage 1 staging)
    u64*   s_X   = (u64*)s_x;                  // 8192 u64 (stage 2; aliases s_x)

    const int tid = threadIdx.x;

    // twiddle tables: theta = 2*pi*tid/256  -> sincospif(tid/128)
    {
        float sn, cs;
        sincospif((float)tid * (1.0f / 128.0f), &sn, &cs);
        s_tw[tid]  = pack2(cs, -sn);   // (cos, -sin)
        s_twB[tid] = pack2(sn,  cs);   // (sin,  cos)
    }

    // ---- stage 1: thread owns k1 in {p, p+8, p+16, p+24}, n2 in {q + 32j} ----
    const int q = tid & 31;   // n2 lane (conflict-free smem banks)
    const int p = tid >> 5;   // 0..7
    u64 acc[4][8];
#pragma unroll
    for (int m = 0; m < 4; m++)
#pragma unroll
        for (int j = 0; j < 8; j++) acc[m][j] = 0ull;

    __syncthreads();

    for (int chunk = 0; chunk < HH; chunk += 32) {
#pragma unroll
        for (int i = 0; i < 32; i++)
            s_x[i * 256 + tid] = x[(size_t)(chunk + i) * 256 + tid];
        __syncthreads();

        for (int r = 0; r < 32; r++) {
            const int n1 = chunk + r;
            const u64 t0 = s_tw[(p * n1) & 255];
            const u64 t1 = s_tw[((p + 8)  * n1) & 255];
            const u64 t2 = s_tw[((p + 16) * n1) & 255];
            const u64 t3 = s_tw[((p + 24) * n1) & 255];
            const float* row = s_x + r * 256 + q;
#pragma unroll
            for (int j = 0; j < 8; j++) {
                const float xv = row[32 * j];
                const u64 xv2 = pack2(xv, xv);
                acc[0][j] = ffma2(xv2, t0, acc[0][j]);
                acc[1][j] = ffma2(xv2, t1, acc[1][j]);
                acc[2][j] = ffma2(xv2, t2, acc[2][j]);
                acc[3][j] = ffma2(xv2, t3, acc[3][j]);
            }
        }
        __syncthreads();
    }

    // scatter stage-1 result to smem as [n2][k1] (s_X aliases s_x: stage-1
    // reads are complete, the __syncthreads above orders them before writes)
#pragma unroll
    for (int m = 0; m < 4; m++)
#pragma unroll
        for (int j = 0; j < 8; j++)
            s_X[(q + 32 * j) * 32 + (p + 8 * m)] = acc[m][j];
    __syncthreads();

    // ---- stage 2: thread owns k1 = lane, k2 in {g, g+8, g+16, g+24} ----
    const int k1 = tid & 31;
    const int g  = tid >> 5;
    u64 acc2[4] = {0ull, 0ull, 0ull, 0ull};

    for (int n2 = 0; n2 < 256; n2++) {
        const u64 Xv = s_X[n2 * 32 + k1];
        float Xr, Xi; unpack2(Xv, Xr, Xi);
        const u64 xr2 = pack2(Xr, Xr);
        const u64 xi2 = pack2(Xi, Xi);
#pragma unroll
        for (int r = 0; r < 4; r++) {
            const int idx = ((g + 8 * r) * n2) & 255;
            acc2[r] = ffma2(xr2, s_tw[idx],  acc2[r]);  // (Xr c, -Xr s)
            acc2[r] = ffma2(xi2, s_twB[idx], acc2[r]);  // (Xi s,  Xi c)
        }
    }

    float2* __restrict__ outm = g_modes[sel][img];
    float esum = 0.f;
#pragma unroll
    for (int r = 0; r < 4; r++) {
        float re, im; unpack2(acc2[r], re, im);
        const int k2 = g + 8 * r;
        outm[k2 * 32 + k1] = make_float2(re, im);
        esum += re * re + im * im;
    }

    if (sel == 0) {
        // block-reduce total energy for this image
#pragma unroll
        for (int off = 16; off; off >>= 1)
            esum += __shfl_xor_sync(0xffffffffu, esum, off);
        __syncthreads();               // s_X reads done before scratch reuse
        float* s_red = s_x;
        if ((tid & 31) == 0) s_red[tid >> 5] = esum;
        __syncthreads();
        if (tid == 0) {
            float t = 0.f;
            for (int w = 0; w < 8; w++) t += s_red[w];
            g_tot[img] = t;
        }
    }
}

// ============================================================================
// K3: pointwise energies/errors + per-mode MLP + fractions/weighted.
// grid (512, 4) x 256 threads; one mode per thread.
// W2 repacked in smem as i-major f32x2 pairs -> inner loop 1 LDS64 + 1 FMA2.
// ============================================================================
__global__ void __launch_bounds__(256)
k_mlp(const float* __restrict__ W1, const float* __restrict__ b1,
      const float* __restrict__ W2, const float* __restrict__ b2,
      const float* __restrict__ W3, const float* __restrict__ b3,
      float* __restrict__ o_energy, float* __restrict__ o_unc,
      float* __restrict__ o_frac,   float* __restrict__ o_weight,
      float* __restrict__ o_err)
{
    __shared__ float sW1[128], sb1[64], sb2[32], sW3[32];
    __shared__ float sb3;
    __shared__ u64 sW2t[1024];   // [i][jj] = (W2[2jj][i], W2[2jj+1][i])

    const int tid = threadIdx.x;
    if (tid < 128) sW1[tid] = W1[tid];
    if (tid < 64)  sb1[tid] = b1[tid];
    if (tid < 32)  { sb2[tid] = b2[tid]; sW3[tid] = W3[tid]; }
    if (tid == 0)  sb3 = b3[0];
    for (int idx = tid; idx < 1024; idx += 256) {
        const int i = idx >> 5, jj = idx & 31;
        sW2t[idx] = pack2(W2[(2 * jj) * 32 + i], W2[(2 * jj + 1) * 32 + i]);
    }
    __syncthreads();

    const int img  = blockIdx.x;
    const int midx = blockIdx.y * 256 + tid;     // k1*32 + k2
    const int k1 = midx >> 5, k2 = midx & 31;

    const float2 mp = g_modes[0][img][k2 * 32 + k1];
    const float2 mg = g_modes[1][img][k2 * 32 + k1];

    const float energy = mp.x * mp.x + mp.y * mp.y;
    const float dr = mp.x - mg.x, di = mp.y - mg.y;
    const float err = dr * dr + di * di;

    // layer 1: h1[j] = relu(re*W1[0,j] + im*W1[1,j] + b1[j]) -> packed pairs
    u64 h1p[32];
#pragma unroll
    for (int jj = 0; jj < 32; jj++) {
        const float a = fmaxf(fmaf(mp.y, sW1[64 + 2 * jj],
                              fmaf(mp.x, sW1[2 * jj], sb1[2 * jj])), 0.f);
        const float b = fmaxf(fmaf(mp.y, sW1[64 + 2 * jj + 1],
                              fmaf(mp.x, sW1[2 * jj + 1], sb1[2 * jj + 1])), 0.f);
        h1p[jj] = pack2(a, b);
    }

    // layer 2 + layer 3
    float out = sb3;
    for (int i = 0; i < 32; i++) {
        u64 a2 = 0ull;
#pragma unroll
        for (int jj = 0; jj < 32; jj++)
            a2 = ffma2(h1p[jj], sW2t[i * 32 + jj], a2);
        float alo, ahi; unpack2(a2, alo, ahi);
        const float h2 = fmaxf(alo + ahi + sb2[i], 0.f);
        out = fmaf(h2, sW3[i], out);
    }
    // softplus (stable, matches jax.nn.softplus)
    const float uval = fmaxf(out, 0.f) + log1pf(expf(-fabsf(out)));

    const float tot  = g_tot[img];
    const float frac = energy / (tot + 1e-8f);

    const size_t base = (size_t)img * 1024 + midx;
    o_energy[base] = energy;
    o_unc[base]    = uval;
    o_frac[base]   = frac;
    o_weight[base] = frac * uval;
    o_err[base]    = err;
}

// ============================================================================
// K4: spectra (means over 512 images) + Pearson calibration per mode.
// 32 blocks x 1024 threads; block handles 32 contiguous modes (coalesced).
// fp64 accumulation (uncentered-sum Pearson is exact enough in double).
// ============================================================================
__global__ void __launch_bounds__(1024)
k_spec(const float* __restrict__ o_unc, const float* __restrict__ o_err,
       const float* __restrict__ o_energy,
       float* __restrict__ o_uspec, float* __restrict__ o_espec,
       float* __restrict__ o_calib)
{
    __shared__ double sp[32][32][6];   // [grp][m][stat] = 48KB
    const int tid = threadIdx.x;
    const int m = tid & 31, grp = tid >> 5;
    const int mode = blockIdx.x * 32 + m;

    double su = 0, se = 0, sen = 0, suu = 0, see = 0, sue = 0;
    for (int img = grp; img < NIMG; img += 32) {
        const size_t off = (size_t)img * 1024 + mode;
        const double u  = o_unc[off];
        const double e  = o_err[off];
        const double en = o_energy[off];
        su += u; se += e; sen += en;
        suu += u * u; see += e * e; sue += u * e;
    }
    sp[grp][m][0] = su;  sp[grp][m][1] = se;  sp[grp][m][2] = sen;
    sp[grp][m][3] = suu; sp[grp][m][4] = see; sp[grp][m][5] = sue;
    __syncthreads();

    if (tid < 32) {
        double a0 = 0, a1 = 0, a2 = 0, a3 = 0, a4 = 0, a5 = 0;
        for (int g2 = 0; g2 < 32; g2++) {
            a0 += sp[g2][tid][0]; a1 += sp[g2][tid][1]; a2 += sp[g2][tid][2];
            a3 += sp[g2][tid][3]; a4 += sp[g2][tid][4]; a5 += sp[g2][tid][5];
        }
        const double N = (double)NIMG;
        const int md = blockIdx.x * 32 + tid;
        o_uspec[md] = (float)(a0 / N);
        o_espec[md] = (float)(a2 / N);
        const double num = a5 - a0 * a1 / N;
        const double A   = a3 - a0 * a0 / N;
        const double Bv  = a4 - a1 * a1 / N;
        const double den = sqrt(fmax(A * Bv, 0.0));
        o_calib[md] = (float)(num / (den + 1e-8));
    }
}

// ============================================================================
// launch
// inputs: 0 prediction, 1 uncertainty (UNUSED), 2 ground_truth,
//         3 W1[2,64], 4 b1[64], 5 W2[64,32], 6 b2[32], 7 W3[32,1], 8 b3[1]
// output (fp32, concatenated in reference-tuple order):
//   energies | uncertainties | fractions | weighted | uspec | espec | errors | calib
// ============================================================================
extern "C" void kernel_launch(void* const* d_in, const int* in_sizes, int n_in,
                              void* d_out, int out_size)
{
    const float* pred = (const float*)d_in[0];
    const float* gt   = (const float*)d_in[2];
    const float* W1 = (const float*)d_in[3];
    const float* b1 = (const float*)d_in[4];
    const float* W2 = (const float*)d_in[5];
    const float* b2 = (const float*)d_in[6];
    const float* W3 = (const float*)d_in[7];
    const float* b3 = (const float*)d_in[8];

    float* out = (float*)d_out;
    const size_t NM = (size_t)NMODES;
    float* o_energy = out;
    float* o_unc    = out + NM;
    float* o_frac   = out + 2 * NM;
    float* o_weight = out + 3 * NM;
    float* o_uspec  = out + 4 * NM;
    float* o_espec  = o_uspec + 1024;
    float* o_err    = o_espec + 1024;
    float* o_calib  = o_err + NM;

    // 4KB twiddles + 64KB stage-2 buffer (stage-1 32KB staging aliases it)
    const int smem_dft = 256 * 8 * 2 + 8192 * 8; // 69632 B
    static int attr_done = 0;
    if (!attr_done) {
        cudaFuncSetAttribute(k_dft, cudaFuncAttributeMaxDynamicSharedMemorySize, smem_dft);
        attr_done = 1;
    }

    k_dft<<<dim3(NIMG, 2), 256, smem_dft>>>(pred, gt);
    k_mlp<<<dim3(NIMG, 4), 256>>>(W1, b1, W2, b2, W3, b3,
                                  o_energy, o_unc, o_frac, o_weight, o_err);
    k_spec<<<32, 1024>>>(o_unc, o_err, o_energy, o_uspec, o_espec, o_calib);
}